// round 6
// baseline (speedup 1.0000x reference)
#include <cuda_runtime.h>
#include <math.h>

// Problem dims
#define BSz 4
#define Nn  256
#define DXx 256
#define DEe 64
#define DYy 64
#define NHh 8
#define DFf 32

// Output layout: newX (4,256,256) | newE (4,256,256,64) | newY (4,64)
#define OFF_NEWX 0
#define OFF_NEWE 262144
#define OFF_NEWY 17039360

// ---------------- scratch (no runtime allocs allowed) ----------------
__device__ __align__(16) float g_q[BSz*Nn*DXx];    // masked & pre-scaled by 1/sqrt(DF)
__device__ __align__(16) float g_k[BSz*Nn*DXx];    // masked
__device__ __align__(16) float g_v[BSz*Nn*DXx];    // masked
__device__ __align__(16) float g_yx1[BSz*DXx];
__device__ __align__(16) float g_yx2[BSz*DXx];
__device__ __align__(16) float g_W2 [BSz*DXx*DEe]; // (ye2+1)*We_out
__device__ __align__(16) float g_cst[BSz*DEe];     // sum_f ye1*We_out + be_out
__device__ __align__(16) float g_xpool[BSz*4*DXx]; // mean|min|max|std over i
__device__ __align__(16) float g_ep[BSz*16*4*DEe]; // partial e-pool (16 chunks)

// ---------------- q,k,v projections ----------------
__global__ void __launch_bounds__(256) k_qkv(
    const float* __restrict__ x, const float* __restrict__ Wq,
    const float* __restrict__ Wk, const float* __restrict__ Wv,
    const float* __restrict__ mask)
{
    __shared__ __align__(16) float xs[DXx];
    int b = blockIdx.x >> 8, i = blockIdx.x & 255;
    int f = threadIdx.x;
    xs[f] = x[(b*Nn + i)*DXx + f];
    __syncthreads();
    float q = 0.f, k = 0.f, v = 0.f;
#pragma unroll 1
    for (int d = 0; d < DXx; d += 4) {
        float4 x4 = *reinterpret_cast<const float4*>(&xs[d]);
        const float* wq = Wq + d*DXx + f;
        const float* wk = Wk + d*DXx + f;
        const float* wv = Wv + d*DXx + f;
        q = fmaf(x4.x, wq[0], q); q = fmaf(x4.y, wq[DXx], q);
        q = fmaf(x4.z, wq[2*DXx], q); q = fmaf(x4.w, wq[3*DXx], q);
        k = fmaf(x4.x, wk[0], k); k = fmaf(x4.y, wk[DXx], k);
        k = fmaf(x4.z, wk[2*DXx], k); k = fmaf(x4.w, wk[3*DXx], k);
        v = fmaf(x4.x, wv[0], v); v = fmaf(x4.y, wv[DXx], v);
        v = fmaf(x4.z, wv[2*DXx], v); v = fmaf(x4.w, wv[3*DXx], v);
    }
    float mi = mask[b*Nn + i];
    int o = (b*Nn + i)*DXx + f;
    g_q[o] = q * mi * 0.17677669529663688f;  // 1/sqrt(32)
    g_k[o] = k * mi;
    g_v[o] = v * mi;
}

// ---------------- y-side projections + W2 + const ----------------
__global__ void __launch_bounds__(256) k_ypre(
    const float* __restrict__ y,
    const float* __restrict__ Wye_add, const float* __restrict__ Wye_mul,
    const float* __restrict__ Wyx_add, const float* __restrict__ Wyx_mul,
    const float* __restrict__ We_out,  const float* __restrict__ be_out)
{
    __shared__ float ye1s[BSz*DXx];
    int f = threadIdx.x;
    for (int b = 0; b < BSz; ++b) {
        float a = 0.f, m = 0.f, xa = 0.f, xm = 0.f;
#pragma unroll 1
        for (int d = 0; d < DYy; ++d) {
            float yv = y[b*DYy + d];
            a  = fmaf(yv, Wye_add[d*DXx + f], a);
            m  = fmaf(yv, Wye_mul[d*DXx + f], m);
            xa = fmaf(yv, Wyx_add[d*DXx + f], xa);
            xm = fmaf(yv, Wyx_mul[d*DXx + f], xm);
        }
        g_yx1[b*DXx + f] = xa;
        g_yx2[b*DXx + f] = xm;
        ye1s[b*DXx + f] = a;
        float coef = m + 1.0f;
#pragma unroll
        for (int c = 0; c < DEe; c += 4) {
            float4 w = *reinterpret_cast<const float4*>(&We_out[f*DEe + c]);
            float4 o;
            o.x = coef*w.x; o.y = coef*w.y; o.z = coef*w.z; o.w = coef*w.w;
            *reinterpret_cast<float4*>(&g_W2[(b*DXx + f)*DEe + c]) = o;
        }
    }
    __syncthreads();
    int b = f >> 6, c = f & 63;
    float s = be_out[c];
#pragma unroll 1
    for (int ff = 0; ff < DXx; ++ff)
        s = fmaf(ye1s[b*DXx + ff], We_out[ff*DEe + c], s);
    g_cst[b*DEe + c] = s;
}

// ---------------- x pool over i ----------------
__global__ void __launch_bounds__(256) k_xpool(const float* __restrict__ x)
{
    int b = blockIdx.x, f = threadIdx.x;
    float s = 0.f, ss = 0.f, mn = 1e30f, mx = -1e30f;
#pragma unroll 1
    for (int i = 0; i < Nn; ++i) {
        float v = x[(b*Nn + i)*DXx + f];
        s += v; ss = fmaf(v, v, ss);
        mn = fminf(mn, v); mx = fmaxf(mx, v);
    }
    float M = (float)Nn;
    float mean = s / M;
    float var = (ss - s*s/M) / (M - 1.0f);
    float* dst = &g_xpool[b*4*DXx];
    dst[0*DXx + f] = mean;
    dst[1*DXx + f] = mn;
    dst[2*DXx + f] = mx;
    dst[3*DXx + f] = sqrtf(fmaxf(var, 0.f));
}

// ---------------- e pool stage 1 (partials over 16-row chunks) ----------------
__global__ void __launch_bounds__(256) k_epool1(const float* __restrict__ e)
{
    int b = blockIdx.y, ch = blockIdx.x;
    int t = threadIdx.x;
    int c = t & 63, sl = t >> 6;           // 4 slices of 4 i-rows
    float s = 0.f, ss = 0.f, mn = 1e30f, mx = -1e30f;
    int i0 = ch*16 + sl*4;
#pragma unroll 1
    for (int i = i0; i < i0 + 4; ++i) {
#pragma unroll 4
        for (int j = 0; j < Nn; ++j) {
            float v = e[((b*Nn + i)*Nn + j)*DEe + c];
            s += v; ss = fmaf(v, v, ss);
            mn = fminf(mn, v); mx = fmaxf(mx, v);
        }
    }
    __shared__ float shs[4][64], shss[4][64], shmn[4][64], shmx[4][64];
    shs[sl][c] = s; shss[sl][c] = ss; shmn[sl][c] = mn; shmx[sl][c] = mx;
    __syncthreads();
    if (sl == 0) {
#pragma unroll
        for (int s2 = 1; s2 < 4; ++s2) {
            s += shs[s2][c]; ss += shss[s2][c];
            mn = fminf(mn, shmn[s2][c]); mx = fmaxf(mx, shmx[s2][c]);
        }
        float* dst = &g_ep[((b*16 + ch)*4)*64];
        dst[0*64 + c] = s;  dst[1*64 + c] = ss;
        dst[2*64 + c] = mn; dst[3*64 + c] = mx;
    }
}

// ---------------- newY (pools combine + small matmuls) ----------------
__global__ void __launch_bounds__(256) k_final(
    const float* __restrict__ y,   const float* __restrict__ Wyy,
    const float* __restrict__ Wxy, const float* __restrict__ bxy,
    const float* __restrict__ Wey, const float* __restrict__ bey,
    const float* __restrict__ Wy_out, const float* __restrict__ by_out,
    float* __restrict__ out_newY)
{
    __shared__ float ep[BSz][4*DEe];
    __shared__ float tot[BSz][DYy];
    int t = threadIdx.x;
    int b = t >> 6, dy = t & 63;
    {   // combine e-pool partials
        int c = dy;
        float s = 0.f, ss = 0.f, mn = 1e30f, mx = -1e30f;
#pragma unroll 1
        for (int ch = 0; ch < 16; ++ch) {
            const float* p = &g_ep[((b*16 + ch)*4)*64];
            s += p[0*64 + c]; ss += p[1*64 + c];
            mn = fminf(mn, p[2*64 + c]); mx = fmaxf(mx, p[3*64 + c]);
        }
        float M = (float)(Nn*Nn);
        ep[b][0*DEe + c] = s / M;
        ep[b][1*DEe + c] = mn;
        ep[b][2*DEe + c] = mx;
        ep[b][3*DEe + c] = sqrtf(fmaxf((ss - s*s/M)/(M - 1.0f), 0.f));
    }
    __syncthreads();
    float xy = bxy[dy];
#pragma unroll 1
    for (int p = 0; p < 4*DXx; ++p)
        xy = fmaf(g_xpool[b*4*DXx + p], Wxy[p*DYy + dy], xy);
    float ey = bey[dy];
#pragma unroll 1
    for (int p = 0; p < 4*DEe; ++p)
        ey = fmaf(ep[b][p], Wey[p*DYy + dy], ey);
    float yy = 0.f;
#pragma unroll 1
    for (int d = 0; d < DYy; ++d)
        yy = fmaf(y[b*DYy + d], Wyy[d*DYy + dy], yy);
    tot[b][dy] = xy + ey + yy;
    __syncthreads();
    float o = by_out[dy];
#pragma unroll 1
    for (int d = 0; d < DYy; ++d)
        o = fmaf(tot[b][d], Wy_out[d*DYy + dy], o);
    out_newY[b*DYy + dy] = o;
}

// ---------------- main fused kernel: e1/e2, Y, newE, softmax-attn, newX ----------------
__global__ void __launch_bounds__(256, 3) k_main(
    const float* __restrict__ e, const float* __restrict__ node_mask,
    const float* __restrict__ We_mul, const float* __restrict__ We_add,
    const float* __restrict__ Wx_out, const float* __restrict__ bx_out,
    float* __restrict__ out)
{
    __shared__ __align__(16) float e_sh[16][64];    // e chunk (16 j rows)
    __shared__ __align__(16) float Ysh[16][DXx];    // Y tile for projection

    int b = blockIdx.x >> 8, i = blockIdx.x & 255;
    int f = threadIdx.x;
    float mi = node_mask[b*Nn + i];
    float qf = g_q[(b*Nn + i)*DXx + f];

    // online softmax state (per feature f, over j)
    float m = -1e30f, ssum = 0.f, acc = 0.f;

    const float* __restrict__ erow = e + ((b*Nn + i)*Nn)*DEe;
    // projection thread mapping: one (jt, 4-wide c) tile per thread
    int jt_p = f >> 4;
    int c0   = (f & 15) * 4;
    float4 cst4 = *reinterpret_cast<const float4*>(&g_cst[b*DEe + c0]);
    const float* __restrict__ W2b = g_W2 + b*DXx*DEe;
    float* __restrict__ outE = out + OFF_NEWE + (size_t)(b*Nn + i)*Nn*DEe;

    for (int jc = 0; jc < 16; ++jc) {
        int j0 = jc * 16;
        // stage e chunk (1024 contiguous floats)
        reinterpret_cast<float4*>(e_sh)[f] =
            reinterpret_cast<const float4*>(erow + j0*DEe)[f];
        __syncthreads();

        float e1a[16], e2a[16];
#pragma unroll
        for (int jt = 0; jt < 16; ++jt) { e1a[jt] = 0.f; e2a[jt] = 0.f; }
#pragma unroll 1
        for (int kk = 0; kk < 64; kk += 4) {
            const float* wmp = We_mul + kk*DXx + f;
            const float* wap = We_add + kk*DXx + f;
            float wm0 = wmp[0], wm1 = wmp[DXx], wm2 = wmp[2*DXx], wm3 = wmp[3*DXx];
            float wa0 = wap[0], wa1 = wap[DXx], wa2 = wap[2*DXx], wa3 = wap[3*DXx];
#pragma unroll
            for (int jt = 0; jt < 16; ++jt) {
                float4 e4 = *reinterpret_cast<const float4*>(&e_sh[jt][kk]);
                float t1 = e1a[jt], t2 = e2a[jt];
                t1 = fmaf(e4.x, wm0, t1); t1 = fmaf(e4.y, wm1, t1);
                t1 = fmaf(e4.z, wm2, t1); t1 = fmaf(e4.w, wm3, t1);
                t2 = fmaf(e4.x, wa0, t2); t2 = fmaf(e4.y, wa1, t2);
                t2 = fmaf(e4.z, wa2, t2); t2 = fmaf(e4.w, wa3, t2);
                e1a[jt] = t1; e2a[jt] = t2;
            }
        }

        // form Y, stage it, update online softmax
#pragma unroll
        for (int jt = 0; jt < 16; ++jt) {
            int j = j0 + jt;
            float mj = node_mask[b*Nn + j];
            float em = mi * mj;
            float kj = g_k[(b*Nn + j)*DXx + f];
            float vj = g_v[(b*Nn + j)*DXx + f];
            // Y = (q*k/sqrt(df)) * (e1*em + 1) + e2*em   (q pre-scaled)
            float yv = fmaf(qf*kj, fmaf(e1a[jt], em, 1.0f), e2a[jt]*em);
            Ysh[jt][f] = yv;
            float ym = (mj > 0.f) ? yv : -1e9f;
            float nm = fmaxf(m, ym);
            float p    = __expf(ym - nm);
            float corr = __expf(m  - nm);
            ssum = fmaf(ssum, corr, p);
            acc  = fmaf(acc,  corr, p*vj);
            m = nm;
        }
        __syncthreads();

        // newE projection: Ytile(16x256) @ W2b(256x64) + const, *em
        float a0 = 0.f, a1 = 0.f, a2 = 0.f, a3 = 0.f;
        const float* __restrict__ yrow = Ysh[jt_p];
        const float* __restrict__ w2p = W2b + c0;
#pragma unroll 4
        for (int ff = 0; ff < DXx; ff += 4) {
            float4 y4 = *reinterpret_cast<const float4*>(&yrow[ff]);
            float4 w0 = *reinterpret_cast<const float4*>(&w2p[(ff+0)*DEe]);
            float4 w1 = *reinterpret_cast<const float4*>(&w2p[(ff+1)*DEe]);
            float4 w2 = *reinterpret_cast<const float4*>(&w2p[(ff+2)*DEe]);
            float4 w3 = *reinterpret_cast<const float4*>(&w2p[(ff+3)*DEe]);
            a0 = fmaf(y4.x, w0.x, a0); a0 = fmaf(y4.y, w1.x, a0);
            a0 = fmaf(y4.z, w2.x, a0); a0 = fmaf(y4.w, w3.x, a0);
            a1 = fmaf(y4.x, w0.y, a1); a1 = fmaf(y4.y, w1.y, a1);
            a1 = fmaf(y4.z, w2.y, a1); a1 = fmaf(y4.w, w3.y, a1);
            a2 = fmaf(y4.x, w0.z, a2); a2 = fmaf(y4.y, w1.z, a2);
            a2 = fmaf(y4.z, w2.z, a2); a2 = fmaf(y4.w, w3.z, a2);
            a3 = fmaf(y4.x, w0.w, a3); a3 = fmaf(y4.y, w1.w, a3);
            a3 = fmaf(y4.z, w2.w, a3); a3 = fmaf(y4.w, w3.w, a3);
        }
        {
            int j = j0 + jt_p;
            float em = mi * node_mask[b*Nn + j];
            float4 r;
            r.x = (a0 + cst4.x) * em;
            r.y = (a1 + cst4.y) * em;
            r.z = (a2 + cst4.z) * em;
            r.w = (a3 + cst4.w) * em;
            *reinterpret_cast<float4*>(&outE[(size_t)j*DEe + c0]) = r;
        }
        // next iteration's __syncthreads (after e stage) separates Ysh reuse
    }

    // attention finalize + yx modulation
    float wsum = acc / ssum;
    float tval = fmaf(g_yx2[b*DXx + f] + 1.0f, wsum, g_yx1[b*DXx + f]);
    __syncthreads();
    float* tsh = &e_sh[0][0];
    tsh[f] = tval;
    __syncthreads();

    // newX = t @ Wx_out + bx_out, * mask_i
    float o = bx_out[f];
#pragma unroll 1
    for (int d = 0; d < DXx; d += 4) {
        float4 t4 = *reinterpret_cast<const float4*>(&tsh[d]);
        const float* w = Wx_out + d*DXx + f;
        o = fmaf(t4.x, w[0], o);
        o = fmaf(t4.y, w[DXx], o);
        o = fmaf(t4.z, w[2*DXx], o);
        o = fmaf(t4.w, w[3*DXx], o);
    }
    out[OFF_NEWX + (b*Nn + i)*DXx + f] = o * mi;
}

// ---------------- launch ----------------
extern "C" void kernel_launch(void* const* d_in, const int* in_sizes, int n_in,
                              void* d_out, int out_size)
{
    const float* x        = (const float*)d_in[0];
    const float* e        = (const float*)d_in[1];
    const float* y        = (const float*)d_in[2];
    const float* node_mask= (const float*)d_in[3];
    const float* Wq       = (const float*)d_in[4];
    const float* Wk       = (const float*)d_in[5];
    const float* Wv       = (const float*)d_in[6];
    const float* We_mul   = (const float*)d_in[7];
    const float* We_add   = (const float*)d_in[8];
    const float* Wye_add  = (const float*)d_in[9];
    const float* Wye_mul  = (const float*)d_in[10];
    const float* Wyx_add  = (const float*)d_in[11];
    const float* Wyx_mul  = (const float*)d_in[12];
    const float* Wyy      = (const float*)d_in[13];
    const float* Wxy      = (const float*)d_in[14];
    const float* bxy      = (const float*)d_in[15];
    const float* Wey      = (const float*)d_in[16];
    const float* bey      = (const float*)d_in[17];
    const float* We_out   = (const float*)d_in[18];
    const float* be_out   = (const float*)d_in[19];
    const float* Wx_out   = (const float*)d_in[20];
    const float* bx_out   = (const float*)d_in[21];
    const float* Wy_out   = (const float*)d_in[22];
    const float* by_out   = (const float*)d_in[23];
    float* out = (float*)d_out;

    k_qkv  <<<BSz*Nn, 256>>>(x, Wq, Wk, Wv, node_mask);
    k_ypre <<<1, 256>>>(y, Wye_add, Wye_mul, Wyx_add, Wyx_mul, We_out, be_out);
    k_xpool<<<BSz, 256>>>(x);
    k_epool1<<<dim3(16, BSz), 256>>>(e);
    k_final<<<1, 256>>>(y, Wyy, Wxy, bxy, Wey, bey, Wy_out, by_out, out + OFF_NEWY);
    k_main <<<BSz*Nn, 256>>>(e, node_mask, We_mul, We_add, Wx_out, bx_out, out);
}

// round 8
// speedup vs baseline: 1.0453x; 1.0453x over previous
#include <cuda_runtime.h>
#include <math.h>

// Problem dims
#define BSz 4
#define Nn  256
#define DXx 256
#define DEe 64
#define DYy 64
#define NHh 8
#define DFf 32

// Output layout: newX (4,256,256) | newE (4,256,256,64) | newY (4,64)
#define OFF_NEWX 0
#define OFF_NEWE 262144
#define OFF_NEWY 17039360

// ---------------- scratch (no runtime allocs allowed) ----------------
__device__ __align__(16) float g_q[BSz*Nn*DXx];    // masked & pre-scaled by 1/sqrt(DF)
__device__ __align__(16) float g_k[BSz*Nn*DXx];    // masked
__device__ __align__(16) float g_v[BSz*Nn*DXx];    // masked
__device__ __align__(16) float g_yx1[BSz*DXx];
__device__ __align__(16) float g_yx2[BSz*DXx];
__device__ __align__(16) float g_W2 [BSz*DXx*DEe]; // (ye2+1)*We_out
__device__ __align__(16) float g_cst[BSz*DEe];     // sum_f ye1*We_out + be_out
__device__ __align__(16) float g_xpool[BSz*4*DXx]; // mean|min|max|std over i
__device__ __align__(16) float g_ep[BSz*64*4*DEe]; // partial e-pool (64 chunks of 4 rows)

// ---------------- q,k,v projections ----------------
__global__ void __launch_bounds__(256) k_qkv(
    const float* __restrict__ x, const float* __restrict__ Wq,
    const float* __restrict__ Wk, const float* __restrict__ Wv,
    const float* __restrict__ mask)
{
    __shared__ __align__(16) float xs[DXx];
    int b = blockIdx.x >> 8, i = blockIdx.x & 255;
    int f = threadIdx.x;
    xs[f] = x[(b*Nn + i)*DXx + f];
    __syncthreads();
    float q = 0.f, k = 0.f, v = 0.f;
#pragma unroll 1
    for (int d = 0; d < DXx; d += 4) {
        float4 x4 = *reinterpret_cast<const float4*>(&xs[d]);
        const float* wq = Wq + d*DXx + f;
        const float* wk = Wk + d*DXx + f;
        const float* wv = Wv + d*DXx + f;
        q = fmaf(x4.x, wq[0], q); q = fmaf(x4.y, wq[DXx], q);
        q = fmaf(x4.z, wq[2*DXx], q); q = fmaf(x4.w, wq[3*DXx], q);
        k = fmaf(x4.x, wk[0], k); k = fmaf(x4.y, wk[DXx], k);
        k = fmaf(x4.z, wk[2*DXx], k); k = fmaf(x4.w, wk[3*DXx], k);
        v = fmaf(x4.x, wv[0], v); v = fmaf(x4.y, wv[DXx], v);
        v = fmaf(x4.z, wv[2*DXx], v); v = fmaf(x4.w, wv[3*DXx], v);
    }
    float mi = mask[b*Nn + i];
    int o = (b*Nn + i)*DXx + f;
    g_q[o] = q * mi * 0.17677669529663688f;  // 1/sqrt(32)
    g_k[o] = k * mi;
    g_v[o] = v * mi;
}

// ---------------- y-side projections + W2 + const ----------------
__global__ void __launch_bounds__(256) k_ypre(
    const float* __restrict__ y,
    const float* __restrict__ Wye_add, const float* __restrict__ Wye_mul,
    const float* __restrict__ Wyx_add, const float* __restrict__ Wyx_mul,
    const float* __restrict__ We_out,  const float* __restrict__ be_out)
{
    __shared__ float ye1s[BSz*DXx];
    int f = threadIdx.x;
    for (int b = 0; b < BSz; ++b) {
        float a = 0.f, m = 0.f, xa = 0.f, xm = 0.f;
#pragma unroll 1
        for (int d = 0; d < DYy; ++d) {
            float yv = y[b*DYy + d];
            a  = fmaf(yv, Wye_add[d*DXx + f], a);
            m  = fmaf(yv, Wye_mul[d*DXx + f], m);
            xa = fmaf(yv, Wyx_add[d*DXx + f], xa);
            xm = fmaf(yv, Wyx_mul[d*DXx + f], xm);
        }
        g_yx1[b*DXx + f] = xa;
        g_yx2[b*DXx + f] = xm;
        ye1s[b*DXx + f] = a;
        float coef = m + 1.0f;
#pragma unroll
        for (int c = 0; c < DEe; c += 4) {
            float4 w = *reinterpret_cast<const float4*>(&We_out[f*DEe + c]);
            float4 o;
            o.x = coef*w.x; o.y = coef*w.y; o.z = coef*w.z; o.w = coef*w.w;
            *reinterpret_cast<float4*>(&g_W2[(b*DXx + f)*DEe + c]) = o;
        }
    }
    __syncthreads();
    int b = f >> 6, c = f & 63;
    float s = be_out[c];
#pragma unroll 1
    for (int ff = 0; ff < DXx; ++ff)
        s = fmaf(ye1s[b*DXx + ff], We_out[ff*DEe + c], s);
    g_cst[b*DEe + c] = s;
}

// ---------------- x pool over i ----------------
__global__ void __launch_bounds__(256) k_xpool(const float* __restrict__ x)
{
    int b = blockIdx.x, f = threadIdx.x;
    float s = 0.f, ss = 0.f, mn = 1e30f, mx = -1e30f;
#pragma unroll 1
    for (int i = 0; i < Nn; ++i) {
        float v = x[(b*Nn + i)*DXx + f];
        s += v; ss = fmaf(v, v, ss);
        mn = fminf(mn, v); mx = fmaxf(mx, v);
    }
    float M = (float)Nn;
    float mean = s / M;
    float var = (ss - s*s/M) / (M - 1.0f);
    float* dst = &g_xpool[b*4*DXx];
    dst[0*DXx + f] = mean;
    dst[1*DXx + f] = mn;
    dst[2*DXx + f] = mx;
    dst[3*DXx + f] = sqrtf(fmaxf(var, 0.f));
}

// ---------------- e pool stage 1: 64 chunks of 4 i-rows, float4 loads ----------------
__global__ void __launch_bounds__(256) k_epool1(const float* __restrict__ e)
{
    int b = blockIdx.y, ch = blockIdx.x;     // ch in [0,64)
    int t = threadIdx.x;
    int qg = t & 15;                          // 4-column group: cols 4qg..4qg+3
    int jp = t >> 4;                          // j phase 0..15
    float4 s  = make_float4(0.f,0.f,0.f,0.f);
    float4 ss = make_float4(0.f,0.f,0.f,0.f);
    float4 mn = make_float4(1e30f,1e30f,1e30f,1e30f);
    float4 mx = make_float4(-1e30f,-1e30f,-1e30f,-1e30f);
    int i0 = ch * 4;
#pragma unroll 1
    for (int i = i0; i < i0 + 4; ++i) {
        const float4* __restrict__ base =
            reinterpret_cast<const float4*>(e) + (size_t)((b*Nn + i)*Nn)*16;
#pragma unroll 4
        for (int j = jp; j < Nn; j += 16) {
            float4 v = base[j*16 + qg];
            s.x += v.x; s.y += v.y; s.z += v.z; s.w += v.w;
            ss.x = fmaf(v.x,v.x,ss.x); ss.y = fmaf(v.y,v.y,ss.y);
            ss.z = fmaf(v.z,v.z,ss.z); ss.w = fmaf(v.w,v.w,ss.w);
            mn.x = fminf(mn.x,v.x); mn.y = fminf(mn.y,v.y);
            mn.z = fminf(mn.z,v.z); mn.w = fminf(mn.w,v.w);
            mx.x = fmaxf(mx.x,v.x); mx.y = fmaxf(mx.y,v.y);
            mx.z = fmaxf(mx.z,v.z); mx.w = fmaxf(mx.w,v.w);
        }
    }
    __shared__ float sh[16][4][64];           // [jp][stat][col]
    int c0 = qg*4;
    sh[jp][0][c0+0]=s.x;  sh[jp][0][c0+1]=s.y;  sh[jp][0][c0+2]=s.z;  sh[jp][0][c0+3]=s.w;
    sh[jp][1][c0+0]=ss.x; sh[jp][1][c0+1]=ss.y; sh[jp][1][c0+2]=ss.z; sh[jp][1][c0+3]=ss.w;
    sh[jp][2][c0+0]=mn.x; sh[jp][2][c0+1]=mn.y; sh[jp][2][c0+2]=mn.z; sh[jp][2][c0+3]=mn.w;
    sh[jp][3][c0+0]=mx.x; sh[jp][3][c0+1]=mx.y; sh[jp][3][c0+2]=mx.z; sh[jp][3][c0+3]=mx.w;
    __syncthreads();
    int col = t & 63, st = t >> 6;            // st uniform per warp-pair
    float r = sh[0][st][col];
    if (st < 2) {
#pragma unroll
        for (int p = 1; p < 16; ++p) r += sh[p][st][col];
    } else if (st == 2) {
#pragma unroll
        for (int p = 1; p < 16; ++p) r = fminf(r, sh[p][st][col]);
    } else {
#pragma unroll
        for (int p = 1; p < 16; ++p) r = fmaxf(r, sh[p][st][col]);
    }
    g_ep[(((b*64 + ch)*4) + st)*64 + col] = r;
}

// ---------------- newY (pools combine + small matmuls) ----------------
__global__ void __launch_bounds__(256) k_final(
    const float* __restrict__ y,   const float* __restrict__ Wyy,
    const float* __restrict__ Wxy, const float* __restrict__ bxy,
    const float* __restrict__ Wey, const float* __restrict__ bey,
    const float* __restrict__ Wy_out, const float* __restrict__ by_out,
    float* __restrict__ out_newY)
{
    __shared__ float ep[BSz][4*DEe];
    __shared__ float tot[BSz][DYy];
    int t = threadIdx.x;
    int b = t >> 6, dy = t & 63;
    {   // combine e-pool partials
        int c = dy;
        float s = 0.f, ss = 0.f, mn = 1e30f, mx = -1e30f;
#pragma unroll 1
        for (int ch = 0; ch < 64; ++ch) {
            const float* p = &g_ep[((b*64 + ch)*4)*64];
            s += p[0*64 + c]; ss += p[1*64 + c];
            mn = fminf(mn, p[2*64 + c]); mx = fmaxf(mx, p[3*64 + c]);
        }
        float M = (float)(Nn*Nn);
        ep[b][0*DEe + c] = s / M;
        ep[b][1*DEe + c] = mn;
        ep[b][2*DEe + c] = mx;
        ep[b][3*DEe + c] = sqrtf(fmaxf((ss - s*s/M)/(M - 1.0f), 0.f));
    }
    __syncthreads();
    float xy = bxy[dy];
#pragma unroll 1
    for (int p = 0; p < 4*DXx; ++p)
        xy = fmaf(g_xpool[b*4*DXx + p], Wxy[p*DYy + dy], xy);
    float ey = bey[dy];
#pragma unroll 1
    for (int p = 0; p < 4*DEe; ++p)
        ey = fmaf(ep[b][p], Wey[p*DYy + dy], ey);
    float yy = 0.f;
#pragma unroll 1
    for (int d = 0; d < DYy; ++d)
        yy = fmaf(y[b*DYy + d], Wyy[d*DYy + dy], yy);
    tot[b][dy] = xy + ey + yy;
    __syncthreads();
    float o = by_out[dy];
#pragma unroll 1
    for (int d = 0; d < DYy; ++d)
        o = fmaf(tot[b][d], Wy_out[d*DYy + dy], o);
    out_newY[b*DYy + dy] = o;
}

// ---------------- main fused kernel: e1/e2, Y, newE, softmax-attn, newX ----------------
__global__ void __launch_bounds__(256, 3) k_main(
    const float* __restrict__ e, const float* __restrict__ node_mask,
    const float* __restrict__ We_mul, const float* __restrict__ We_add,
    const float* __restrict__ Wx_out, const float* __restrict__ bx_out,
    float* __restrict__ out)
{
    __shared__ __align__(16) float e_sh[16][64];    // e chunk (16 j rows)
    __shared__ __align__(16) float Ysh[16][DXx];    // Y tile for projection
    __shared__ float msh[Nn];                       // node_mask row

    int b = blockIdx.x >> 8, i = blockIdx.x & 255;
    int f = threadIdx.x;
    msh[f] = node_mask[b*Nn + f];
    float mi = node_mask[b*Nn + i];
    float qf = g_q[(b*Nn + i)*DXx + f];

    // online softmax state (per feature f, over j)
    float m = -1e30f, ssum = 0.f, acc = 0.f;

    const float* __restrict__ erow = e + ((b*Nn + i)*Nn)*DEe;
    // projection thread mapping: one (jt, 4-wide c) tile per thread
    int jt_p = f >> 4;
    int c0   = (f & 15) * 4;
    float4 cst4 = *reinterpret_cast<const float4*>(&g_cst[b*DEe + c0]);
    const float* __restrict__ W2b = g_W2 + b*DXx*DEe;
    float* __restrict__ outE = out + OFF_NEWE + (size_t)(b*Nn + i)*Nn*DEe;
    __syncthreads();

    for (int jc = 0; jc < 16; ++jc) {
        int j0 = jc * 16;
        // stage e chunk (1024 contiguous floats)
        reinterpret_cast<float4*>(e_sh)[f] =
            reinterpret_cast<const float4*>(erow + j0*DEe)[f];
        __syncthreads();

        float e1a[16], e2a[16];
#pragma unroll
        for (int jt = 0; jt < 16; ++jt) { e1a[jt] = 0.f; e2a[jt] = 0.f; }
#pragma unroll 1
        for (int kk = 0; kk < 64; kk += 4) {
            const float* wmp = We_mul + kk*DXx + f;
            const float* wap = We_add + kk*DXx + f;
            float wm0 = wmp[0], wm1 = wmp[DXx], wm2 = wmp[2*DXx], wm3 = wmp[3*DXx];
            float wa0 = wap[0], wa1 = wap[DXx], wa2 = wap[2*DXx], wa3 = wap[3*DXx];
#pragma unroll
            for (int jt = 0; jt < 16; ++jt) {
                float4 e4 = *reinterpret_cast<const float4*>(&e_sh[jt][kk]);
                float t1 = e1a[jt], t2 = e2a[jt];
                t1 = fmaf(e4.x, wm0, t1); t1 = fmaf(e4.y, wm1, t1);
                t1 = fmaf(e4.z, wm2, t1); t1 = fmaf(e4.w, wm3, t1);
                t2 = fmaf(e4.x, wa0, t2); t2 = fmaf(e4.y, wa1, t2);
                t2 = fmaf(e4.z, wa2, t2); t2 = fmaf(e4.w, wa3, t2);
                e1a[jt] = t1; e2a[jt] = t2;
            }
        }

        // pass 1: form Y, stage it, stash (vj, masked-Y) in dead e1a/e2a regs,
        // track chunk max — ONE corr exp per chunk instead of per element.
        float cm = -1e30f;
#pragma unroll
        for (int jt = 0; jt < 16; ++jt) {
            int j = j0 + jt;
            float mj = msh[j];
            float em = mi * mj;
            float kj = g_k[(b*Nn + j)*DXx + f];
            float vj = g_v[(b*Nn + j)*DXx + f];
            // Y = (q*k/sqrt(df)) * (e1*em + 1) + e2*em   (q pre-scaled)
            float yv = fmaf(qf*kj, fmaf(e1a[jt], em, 1.0f), e2a[jt]*em);
            Ysh[jt][f] = yv;
            float ym = (mj > 0.f) ? yv : -1e9f;
            cm = fmaxf(cm, ym);
            e1a[jt] = vj;
            e2a[jt] = ym;
        }
        float nm = fmaxf(m, cm);
        float corr = __expf(m - nm);
        ssum *= corr; acc *= corr; m = nm;
        __syncthreads();

        // pass 2: single exp per element — register-only, interleaves with the
        // projection's FFMA/LDG stream below (MUFU overlapped under FMA pipe).
#pragma unroll
        for (int jt = 0; jt < 16; ++jt) {
            float p = __expf(e2a[jt] - nm);
            ssum += p;
            acc = fmaf(p, e1a[jt], acc);
        }

        // newE projection: Ytile(16x256) @ W2b(256x64) + const, *em
        float a0 = 0.f, a1 = 0.f, a2 = 0.f, a3 = 0.f;
        const float* __restrict__ yrow = Ysh[jt_p];
        const float* __restrict__ w2p = W2b + c0;
#pragma unroll 4
        for (int ff = 0; ff < DXx; ff += 4) {
            float4 y4 = *reinterpret_cast<const float4*>(&yrow[ff]);
            float4 w0 = *reinterpret_cast<const float4*>(&w2p[(ff+0)*DEe]);
            float4 w1 = *reinterpret_cast<const float4*>(&w2p[(ff+1)*DEe]);
            float4 w2 = *reinterpret_cast<const float4*>(&w2p[(ff+2)*DEe]);
            float4 w3 = *reinterpret_cast<const float4*>(&w2p[(ff+3)*DEe]);
            a0 = fmaf(y4.x, w0.x, a0); a0 = fmaf(y4.y, w1.x, a0);
            a0 = fmaf(y4.z, w2.x, a0); a0 = fmaf(y4.w, w3.x, a0);
            a1 = fmaf(y4.x, w0.y, a1); a1 = fmaf(y4.y, w1.y, a1);
            a1 = fmaf(y4.z, w2.y, a1); a1 = fmaf(y4.w, w3.y, a1);
            a2 = fmaf(y4.x, w0.z, a2); a2 = fmaf(y4.y, w1.z, a2);
            a2 = fmaf(y4.z, w2.z, a2); a2 = fmaf(y4.w, w3.z, a2);
            a3 = fmaf(y4.x, w0.w, a3); a3 = fmaf(y4.y, w1.w, a3);
            a3 = fmaf(y4.z, w2.w, a3); a3 = fmaf(y4.w, w3.w, a3);
        }
        {
            int j = j0 + jt_p;
            float em = mi * msh[j];
            float4 r;
            r.x = (a0 + cst4.x) * em;
            r.y = (a1 + cst4.y) * em;
            r.z = (a2 + cst4.z) * em;
            r.w = (a3 + cst4.w) * em;
            *reinterpret_cast<float4*>(&outE[(size_t)j*DEe + c0]) = r;
        }
        // next iteration's __syncthreads (after e stage) separates Ysh reuse
    }

    // attention finalize + yx modulation
    float wsum = acc / ssum;
    float tval = fmaf(g_yx2[b*DXx + f] + 1.0f, wsum, g_yx1[b*DXx + f]);
    __syncthreads();
    float* tsh = &e_sh[0][0];
    tsh[f] = tval;
    __syncthreads();

    // newX = t @ Wx_out + bx_out, * mask_i
    float o = bx_out[f];
#pragma unroll 1
    for (int d = 0; d < DXx; d += 4) {
        float4 t4 = *reinterpret_cast<const float4*>(&tsh[d]);
        const float* w = Wx_out + d*DXx + f;
        o = fmaf(t4.x, w[0], o);
        o = fmaf(t4.y, w[DXx], o);
        o = fmaf(t4.z, w[2*DXx], o);
        o = fmaf(t4.w, w[3*DXx], o);
    }
    out[OFF_NEWX + (b*Nn + i)*DXx + f] = o * mi;
}

// ---------------- launch ----------------
extern "C" void kernel_launch(void* const* d_in, const int* in_sizes, int n_in,
                              void* d_out, int out_size)
{
    const float* x        = (const float*)d_in[0];
    const float* e        = (const float*)d_in[1];
    const float* y        = (const float*)d_in[2];
    const float* node_mask= (const float*)d_in[3];
    const float* Wq       = (const float*)d_in[4];
    const float* Wk       = (const float*)d_in[5];
    const float* Wv       = (const float*)d_in[6];
    const float* We_mul   = (const float*)d_in[7];
    const float* We_add   = (const float*)d_in[8];
    const float* Wye_add  = (const float*)d_in[9];
    const float* Wye_mul  = (const float*)d_in[10];
    const float* Wyx_add  = (const float*)d_in[11];
    const float* Wyx_mul  = (const float*)d_in[12];
    const float* Wyy      = (const float*)d_in[13];
    const float* Wxy      = (const float*)d_in[14];
    const float* bxy      = (const float*)d_in[15];
    const float* Wey      = (const float*)d_in[16];
    const float* bey      = (const float*)d_in[17];
    const float* We_out   = (const float*)d_in[18];
    const float* be_out   = (const float*)d_in[19];
    const float* Wx_out   = (const float*)d_in[20];
    const float* bx_out   = (const float*)d_in[21];
    const float* Wy_out   = (const float*)d_in[22];
    const float* by_out   = (const float*)d_in[23];
    float* out = (float*)d_out;

    k_qkv  <<<BSz*Nn, 256>>>(x, Wq, Wk, Wv, node_mask);
    k_ypre <<<1, 256>>>(y, Wye_add, Wye_mul, Wyx_add, Wyx_mul, We_out, be_out);
    k_xpool<<<BSz, 256>>>(x);
    k_epool1<<<dim3(64, BSz), 256>>>(e);
    k_final<<<1, 256>>>(y, Wyy, Wxy, bxy, Wey, bey, Wy_out, by_out, out + OFF_NEWY);
    k_main <<<BSz*Nn, 256>>>(e, node_mask, We_mul, We_add, Wx_out, bx_out, out);
}

// round 9
// speedup vs baseline: 1.0638x; 1.0177x over previous
#include <cuda_runtime.h>
#include <cuda_pipeline.h>
#include <math.h>

// Problem dims
#define BSz 4
#define Nn  256
#define DXx 256
#define DEe 64
#define DYy 64
#define NHh 8
#define DFf 32

// Output layout: newX (4,256,256) | newE (4,256,256,64) | newY (4,64)
#define OFF_NEWX 0
#define OFF_NEWE 262144
#define OFF_NEWY 17039360

// ---------------- scratch (no runtime allocs allowed) ----------------
__device__ __align__(16) float g_q[BSz*Nn*DXx];    // masked & pre-scaled by 1/sqrt(DF)
__device__ __align__(16) float g_k[BSz*Nn*DXx];    // masked
__device__ __align__(16) float g_v[BSz*Nn*DXx];    // masked
__device__ __align__(16) float g_yx1[BSz*DXx];
__device__ __align__(16) float g_yx2[BSz*DXx];
__device__ __align__(16) float g_W2 [BSz*DXx*DEe]; // (ye2+1)*We_out
__device__ __align__(16) float g_cst[BSz*DEe];     // sum_f ye1*We_out + be_out
__device__ __align__(16) float g_xpool[BSz*4*DXx]; // mean|min|max|std over i
__device__ __align__(16) float g_ep[BSz*64*4*DEe]; // partial e-pool (64 chunks of 4 rows)

// ---------------- q,k,v projections ----------------
__global__ void __launch_bounds__(256) k_qkv(
    const float* __restrict__ x, const float* __restrict__ Wq,
    const float* __restrict__ Wk, const float* __restrict__ Wv,
    const float* __restrict__ mask)
{
    __shared__ __align__(16) float xs[DXx];
    int b = blockIdx.x >> 8, i = blockIdx.x & 255;
    int f = threadIdx.x;
    xs[f] = x[(b*Nn + i)*DXx + f];
    __syncthreads();
    float q = 0.f, k = 0.f, v = 0.f;
#pragma unroll 1
    for (int d = 0; d < DXx; d += 4) {
        float4 x4 = *reinterpret_cast<const float4*>(&xs[d]);
        const float* wq = Wq + d*DXx + f;
        const float* wk = Wk + d*DXx + f;
        const float* wv = Wv + d*DXx + f;
        q = fmaf(x4.x, wq[0], q); q = fmaf(x4.y, wq[DXx], q);
        q = fmaf(x4.z, wq[2*DXx], q); q = fmaf(x4.w, wq[3*DXx], q);
        k = fmaf(x4.x, wk[0], k); k = fmaf(x4.y, wk[DXx], k);
        k = fmaf(x4.z, wk[2*DXx], k); k = fmaf(x4.w, wk[3*DXx], k);
        v = fmaf(x4.x, wv[0], v); v = fmaf(x4.y, wv[DXx], v);
        v = fmaf(x4.z, wv[2*DXx], v); v = fmaf(x4.w, wv[3*DXx], v);
    }
    float mi = mask[b*Nn + i];
    int o = (b*Nn + i)*DXx + f;
    g_q[o] = q * mi * 0.17677669529663688f;  // 1/sqrt(32)
    g_k[o] = k * mi;
    g_v[o] = v * mi;
}

// ---------------- y-side projections + W2 + const ----------------
__global__ void __launch_bounds__(256) k_ypre(
    const float* __restrict__ y,
    const float* __restrict__ Wye_add, const float* __restrict__ Wye_mul,
    const float* __restrict__ Wyx_add, const float* __restrict__ Wyx_mul,
    const float* __restrict__ We_out,  const float* __restrict__ be_out)
{
    __shared__ float ye1s[BSz*DXx];
    int f = threadIdx.x;
    for (int b = 0; b < BSz; ++b) {
        float a = 0.f, m = 0.f, xa = 0.f, xm = 0.f;
#pragma unroll 1
        for (int d = 0; d < DYy; ++d) {
            float yv = y[b*DYy + d];
            a  = fmaf(yv, Wye_add[d*DXx + f], a);
            m  = fmaf(yv, Wye_mul[d*DXx + f], m);
            xa = fmaf(yv, Wyx_add[d*DXx + f], xa);
            xm = fmaf(yv, Wyx_mul[d*DXx + f], xm);
        }
        g_yx1[b*DXx + f] = xa;
        g_yx2[b*DXx + f] = xm;
        ye1s[b*DXx + f] = a;
        float coef = m + 1.0f;
#pragma unroll
        for (int c = 0; c < DEe; c += 4) {
            float4 w = *reinterpret_cast<const float4*>(&We_out[f*DEe + c]);
            float4 o;
            o.x = coef*w.x; o.y = coef*w.y; o.z = coef*w.z; o.w = coef*w.w;
            *reinterpret_cast<float4*>(&g_W2[(b*DXx + f)*DEe + c]) = o;
        }
    }
    __syncthreads();
    int b = f >> 6, c = f & 63;
    float s = be_out[c];
#pragma unroll 1
    for (int ff = 0; ff < DXx; ++ff)
        s = fmaf(ye1s[b*DXx + ff], We_out[ff*DEe + c], s);
    g_cst[b*DEe + c] = s;
}

// ---------------- x pool over i ----------------
__global__ void __launch_bounds__(256) k_xpool(const float* __restrict__ x)
{
    int b = blockIdx.x, f = threadIdx.x;
    float s = 0.f, ss = 0.f, mn = 1e30f, mx = -1e30f;
#pragma unroll 1
    for (int i = 0; i < Nn; ++i) {
        float v = x[(b*Nn + i)*DXx + f];
        s += v; ss = fmaf(v, v, ss);
        mn = fminf(mn, v); mx = fmaxf(mx, v);
    }
    float M = (float)Nn;
    float mean = s / M;
    float var = (ss - s*s/M) / (M - 1.0f);
    float* dst = &g_xpool[b*4*DXx];
    dst[0*DXx + f] = mean;
    dst[1*DXx + f] = mn;
    dst[2*DXx + f] = mx;
    dst[3*DXx + f] = sqrtf(fmaxf(var, 0.f));
}

// ---------------- e pool stage 1: 64 chunks of 4 i-rows, float4 loads ----------------
__global__ void __launch_bounds__(256) k_epool1(const float* __restrict__ e)
{
    int b = blockIdx.y, ch = blockIdx.x;     // ch in [0,64)
    int t = threadIdx.x;
    int qg = t & 15;                          // 4-column group: cols 4qg..4qg+3
    int jp = t >> 4;                          // j phase 0..15
    float4 s  = make_float4(0.f,0.f,0.f,0.f);
    float4 ss = make_float4(0.f,0.f,0.f,0.f);
    float4 mn = make_float4(1e30f,1e30f,1e30f,1e30f);
    float4 mx = make_float4(-1e30f,-1e30f,-1e30f,-1e30f);
    int i0 = ch * 4;
#pragma unroll 1
    for (int i = i0; i < i0 + 4; ++i) {
        const float4* __restrict__ base =
            reinterpret_cast<const float4*>(e) + (size_t)((b*Nn + i)*Nn)*16;
#pragma unroll 4
        for (int j = jp; j < Nn; j += 16) {
            float4 v = base[j*16 + qg];
            s.x += v.x; s.y += v.y; s.z += v.z; s.w += v.w;
            ss.x = fmaf(v.x,v.x,ss.x); ss.y = fmaf(v.y,v.y,ss.y);
            ss.z = fmaf(v.z,v.z,ss.z); ss.w = fmaf(v.w,v.w,ss.w);
            mn.x = fminf(mn.x,v.x); mn.y = fminf(mn.y,v.y);
            mn.z = fminf(mn.z,v.z); mn.w = fminf(mn.w,v.w);
            mx.x = fmaxf(mx.x,v.x); mx.y = fmaxf(mx.y,v.y);
            mx.z = fmaxf(mx.z,v.z); mx.w = fmaxf(mx.w,v.w);
        }
    }
    __shared__ float sh[16][4][64];           // [jp][stat][col]
    int c0 = qg*4;
    sh[jp][0][c0+0]=s.x;  sh[jp][0][c0+1]=s.y;  sh[jp][0][c0+2]=s.z;  sh[jp][0][c0+3]=s.w;
    sh[jp][1][c0+0]=ss.x; sh[jp][1][c0+1]=ss.y; sh[jp][1][c0+2]=ss.z; sh[jp][1][c0+3]=ss.w;
    sh[jp][2][c0+0]=mn.x; sh[jp][2][c0+1]=mn.y; sh[jp][2][c0+2]=mn.z; sh[jp][2][c0+3]=mn.w;
    sh[jp][3][c0+0]=mx.x; sh[jp][3][c0+1]=mx.y; sh[jp][3][c0+2]=mx.z; sh[jp][3][c0+3]=mx.w;
    __syncthreads();
    int col = t & 63, st = t >> 6;            // st uniform per warp-pair
    float r = sh[0][st][col];
    if (st < 2) {
#pragma unroll
        for (int p = 1; p < 16; ++p) r += sh[p][st][col];
    } else if (st == 2) {
#pragma unroll
        for (int p = 1; p < 16; ++p) r = fminf(r, sh[p][st][col]);
    } else {
#pragma unroll
        for (int p = 1; p < 16; ++p) r = fmaxf(r, sh[p][st][col]);
    }
    g_ep[(((b*64 + ch)*4) + st)*64 + col] = r;
}

// ---------------- newY (pools combine + small matmuls) ----------------
__global__ void __launch_bounds__(256) k_final(
    const float* __restrict__ y,   const float* __restrict__ Wyy,
    const float* __restrict__ Wxy, const float* __restrict__ bxy,
    const float* __restrict__ Wey, const float* __restrict__ bey,
    const float* __restrict__ Wy_out, const float* __restrict__ by_out,
    float* __restrict__ out_newY)
{
    __shared__ float ep[BSz][4*DEe];
    __shared__ float tot[BSz][DYy];
    int t = threadIdx.x;
    int b = t >> 6, dy = t & 63;
    {   // combine e-pool partials
        int c = dy;
        float s = 0.f, ss = 0.f, mn = 1e30f, mx = -1e30f;
#pragma unroll 1
        for (int ch = 0; ch < 64; ++ch) {
            const float* p = &g_ep[((b*64 + ch)*4)*64];
            s += p[0*64 + c]; ss += p[1*64 + c];
            mn = fminf(mn, p[2*64 + c]); mx = fmaxf(mx, p[3*64 + c]);
        }
        float M = (float)(Nn*Nn);
        ep[b][0*DEe + c] = s / M;
        ep[b][1*DEe + c] = mn;
        ep[b][2*DEe + c] = mx;
        ep[b][3*DEe + c] = sqrtf(fmaxf((ss - s*s/M)/(M - 1.0f), 0.f));
    }
    __syncthreads();
    float xy = bxy[dy];
#pragma unroll 1
    for (int p = 0; p < 4*DXx; ++p)
        xy = fmaf(g_xpool[b*4*DXx + p], Wxy[p*DYy + dy], xy);
    float ey = bey[dy];
#pragma unroll 1
    for (int p = 0; p < 4*DEe; ++p)
        ey = fmaf(ep[b][p], Wey[p*DYy + dy], ey);
    float yy = 0.f;
#pragma unroll 1
    for (int d = 0; d < DYy; ++d)
        yy = fmaf(y[b*DYy + d], Wyy[d*DYy + dy], yy);
    tot[b][dy] = xy + ey + yy;
    __syncthreads();
    float o = by_out[dy];
#pragma unroll 1
    for (int d = 0; d < DYy; ++d)
        o = fmaf(tot[b][d], Wy_out[d*DYy + dy], o);
    out_newY[b*DYy + dy] = o;
}

// ---------------- main fused kernel: e1/e2, Y, newE, softmax-attn, newX ----------------
// dynamic smem layout (floats):
//   W2sh  [256*64]      = 16384   (per-batch modulated We_out, staged once)
//   Ysh   [16][256]     =  4096
//   e_sh  [2][16*64]    =  2048   (double-buffered e chunk, cp.async)
//   msh   [256]         =   256
#define SM_W2   0
#define SM_Y    16384
#define SM_E    (16384 + 4096)
#define SM_M    (16384 + 4096 + 2048)
#define SM_TOT  (16384 + 4096 + 2048 + 256)

__global__ void __launch_bounds__(256, 2) k_main(
    const float* __restrict__ e, const float* __restrict__ node_mask,
    const float* __restrict__ We_mul, const float* __restrict__ We_add,
    const float* __restrict__ Wx_out, const float* __restrict__ bx_out,
    float* __restrict__ out)
{
    extern __shared__ __align__(16) float sm[];
    float* __restrict__ W2sh = sm + SM_W2;
    float* __restrict__ Ysh  = sm + SM_Y;    // [16][256]
    float* __restrict__ e_db = sm + SM_E;    // [2][1024]
    float* __restrict__ msh  = sm + SM_M;

    int b = blockIdx.x >> 8, i = blockIdx.x & 255;
    int f = threadIdx.x;
    msh[f] = node_mask[b*Nn + f];
    // stage W2 (16384 floats) once
    {
        const float4* src = reinterpret_cast<const float4*>(g_W2 + b*DXx*DEe);
        float4* dst = reinterpret_cast<float4*>(W2sh);
#pragma unroll
        for (int t = 0; t < 16; ++t)
            dst[f + t*256] = src[f + t*256];
    }
    float mi = node_mask[b*Nn + i];
    float qf = g_q[(b*Nn + i)*DXx + f];

    // online softmax state (per feature f, over j)
    float m = -1e30f, ssum = 0.f, acc = 0.f;

    const float* __restrict__ erow = e + ((b*Nn + i)*Nn)*DEe;
    // projection thread mapping: one (jt, 4-wide c) tile per thread
    int jt_p = f >> 4;
    int c0   = (f & 15) * 4;
    float4 cst4 = *reinterpret_cast<const float4*>(&g_cst[b*DEe + c0]);
    float* __restrict__ outE = out + OFF_NEWE + (size_t)(b*Nn + i)*Nn*DEe;

    // prefetch e chunk 0
    __pipeline_memcpy_async(e_db + f*4, erow + f*4, 16);
    __pipeline_commit();

    for (int jc = 0; jc < 16; ++jc) {
        int j0 = jc * 16;
        if (jc + 1 < 16) {   // prefetch next chunk into alternate buffer
            __pipeline_memcpy_async(e_db + ((jc+1)&1)*1024 + f*4,
                                    erow + (j0+16)*DEe + f*4, 16);
            __pipeline_commit();
            __pipeline_wait_prior(1);
        } else {
            __pipeline_wait_prior(0);
        }
        __syncthreads();     // current buffer visible to all; Ysh free for reuse
        const float* __restrict__ e_sh = e_db + (jc&1)*1024;  // [16][64]

        float e1a[16], e2a[16];
#pragma unroll
        for (int jt = 0; jt < 16; ++jt) { e1a[jt] = 0.f; e2a[jt] = 0.f; }
#pragma unroll 1
        for (int kk = 0; kk < 64; kk += 4) {
            const float* wmp = We_mul + kk*DXx + f;
            const float* wap = We_add + kk*DXx + f;
            float wm0 = wmp[0], wm1 = wmp[DXx], wm2 = wmp[2*DXx], wm3 = wmp[3*DXx];
            float wa0 = wap[0], wa1 = wap[DXx], wa2 = wap[2*DXx], wa3 = wap[3*DXx];
#pragma unroll
            for (int jt = 0; jt < 16; ++jt) {
                float4 e4 = *reinterpret_cast<const float4*>(&e_sh[jt*64 + kk]);
                float t1 = e1a[jt], t2 = e2a[jt];
                t1 = fmaf(e4.x, wm0, t1); t1 = fmaf(e4.y, wm1, t1);
                t1 = fmaf(e4.z, wm2, t1); t1 = fmaf(e4.w, wm3, t1);
                t2 = fmaf(e4.x, wa0, t2); t2 = fmaf(e4.y, wa1, t2);
                t2 = fmaf(e4.z, wa2, t2); t2 = fmaf(e4.w, wa3, t2);
                e1a[jt] = t1; e2a[jt] = t2;
            }
        }

        // pass 1: form Y, stage it, stash (vj, masked-Y) in dead e1a/e2a regs,
        // track chunk max — ONE corr exp per chunk.
        float cm = -1e30f;
#pragma unroll
        for (int jt = 0; jt < 16; ++jt) {
            int j = j0 + jt;
            float mj = msh[j];
            float em = mi * mj;
            float kj = g_k[(b*Nn + j)*DXx + f];
            float vj = g_v[(b*Nn + j)*DXx + f];
            // Y = (q*k/sqrt(df)) * (e1*em + 1) + e2*em   (q pre-scaled)
            float yv = fmaf(qf*kj, fmaf(e1a[jt], em, 1.0f), e2a[jt]*em);
            Ysh[jt*DXx + f] = yv;
            float ym = (mj > 0.f) ? yv : -1e9f;
            cm = fmaxf(cm, ym);
            e1a[jt] = vj;
            e2a[jt] = ym;
        }
        float nm = fmaxf(m, cm);
        float corr = __expf(m - nm);
        ssum *= corr; acc *= corr; m = nm;
        __syncthreads();

        // pass 2: one exp per element; interleaves with projection FFMA stream
#pragma unroll
        for (int jt = 0; jt < 16; ++jt) {
            float p = __expf(e2a[jt] - nm);
            ssum += p;
            acc = fmaf(p, e1a[jt], acc);
        }

        // newE projection: Ytile(16x256) @ W2sh(256x64) + const, *em  (all smem)
        float a0 = 0.f, a1 = 0.f, a2 = 0.f, a3 = 0.f;
        const float* __restrict__ yrow = Ysh + jt_p*DXx;
        const float* __restrict__ w2p = W2sh + c0;
#pragma unroll 4
        for (int ff = 0; ff < DXx; ff += 4) {
            float4 y4 = *reinterpret_cast<const float4*>(&yrow[ff]);
            float4 w0 = *reinterpret_cast<const float4*>(&w2p[(ff+0)*DEe]);
            float4 w1 = *reinterpret_cast<const float4*>(&w2p[(ff+1)*DEe]);
            float4 w2 = *reinterpret_cast<const float4*>(&w2p[(ff+2)*DEe]);
            float4 w3 = *reinterpret_cast<const float4*>(&w2p[(ff+3)*DEe]);
            a0 = fmaf(y4.x, w0.x, a0); a0 = fmaf(y4.y, w1.x, a0);
            a0 = fmaf(y4.z, w2.x, a0); a0 = fmaf(y4.w, w3.x, a0);
            a1 = fmaf(y4.x, w0.y, a1); a1 = fmaf(y4.y, w1.y, a1);
            a1 = fmaf(y4.z, w2.y, a1); a1 = fmaf(y4.w, w3.y, a1);
            a2 = fmaf(y4.x, w0.z, a2); a2 = fmaf(y4.y, w1.z, a2);
            a2 = fmaf(y4.z, w2.z, a2); a2 = fmaf(y4.w, w3.z, a2);
            a3 = fmaf(y4.x, w0.w, a3); a3 = fmaf(y4.y, w1.w, a3);
            a3 = fmaf(y4.z, w2.w, a3); a3 = fmaf(y4.w, w3.w, a3);
        }
        {
            int j = j0 + jt_p;
            float em = mi * msh[j];
            float4 r;
            r.x = (a0 + cst4.x) * em;
            r.y = (a1 + cst4.y) * em;
            r.z = (a2 + cst4.z) * em;
            r.w = (a3 + cst4.w) * em;
            *reinterpret_cast<float4*>(&outE[(size_t)j*DEe + c0]) = r;
        }
    }

    // attention finalize + yx modulation
    float wsum = acc / ssum;
    float tval = fmaf(g_yx2[b*DXx + f] + 1.0f, wsum, g_yx1[b*DXx + f]);
    __syncthreads();
    float* tsh = e_db;       // reuse
    tsh[f] = tval;
    __syncthreads();

    // newX = t @ Wx_out + bx_out, * mask_i
    float o = bx_out[f];
#pragma unroll 1
    for (int d = 0; d < DXx; d += 4) {
        float4 t4 = *reinterpret_cast<const float4*>(&tsh[d]);
        const float* w = Wx_out + d*DXx + f;
        o = fmaf(t4.x, w[0], o);
        o = fmaf(t4.y, w[DXx], o);
        o = fmaf(t4.z, w[2*DXx], o);
        o = fmaf(t4.w, w[3*DXx], o);
    }
    out[OFF_NEWX + (b*Nn + i)*DXx + f] = o * mi;
}

// ---------------- launch ----------------
extern "C" void kernel_launch(void* const* d_in, const int* in_sizes, int n_in,
                              void* d_out, int out_size)
{
    const float* x        = (const float*)d_in[0];
    const float* e        = (const float*)d_in[1];
    const float* y        = (const float*)d_in[2];
    const float* node_mask= (const float*)d_in[3];
    const float* Wq       = (const float*)d_in[4];
    const float* Wk       = (const float*)d_in[5];
    const float* Wv       = (const float*)d_in[6];
    const float* We_mul   = (const float*)d_in[7];
    const float* We_add   = (const float*)d_in[8];
    const float* Wye_add  = (const float*)d_in[9];
    const float* Wye_mul  = (const float*)d_in[10];
    const float* Wyx_add  = (const float*)d_in[11];
    const float* Wyx_mul  = (const float*)d_in[12];
    const float* Wyy      = (const float*)d_in[13];
    const float* Wxy      = (const float*)d_in[14];
    const float* bxy      = (const float*)d_in[15];
    const float* Wey      = (const float*)d_in[16];
    const float* bey      = (const float*)d_in[17];
    const float* We_out   = (const float*)d_in[18];
    const float* be_out   = (const float*)d_in[19];
    const float* Wx_out   = (const float*)d_in[20];
    const float* bx_out   = (const float*)d_in[21];
    const float* Wy_out   = (const float*)d_in[22];
    const float* by_out   = (const float*)d_in[23];
    float* out = (float*)d_out;

    static int smem_set = -1;
    const int kMainSmem = SM_TOT * (int)sizeof(float);   // 91136 B
    if (smem_set < 0) {
        cudaFuncSetAttribute(k_main, cudaFuncAttributeMaxDynamicSharedMemorySize,
                             kMainSmem);
        smem_set = 1;
    }

    k_qkv  <<<BSz*Nn, 256>>>(x, Wq, Wk, Wv, node_mask);
    k_ypre <<<1, 256>>>(y, Wye_add, Wye_mul, Wyx_add, Wyx_mul, We_out, be_out);
    k_xpool<<<BSz, 256>>>(x);
    k_epool1<<<dim3(64, BSz), 256>>>(e);
    k_final<<<1, 256>>>(y, Wyy, Wxy, bxy, Wey, bey, Wy_out, by_out, out + OFF_NEWY);
    k_main <<<BSz*Nn, 256, kMainSmem>>>(e, node_mask, We_mul, We_add, Wx_out, bx_out, out);
}